// round 1
// baseline (speedup 1.0000x reference)
#include <cuda_runtime.h>
#include <math.h>

#define BATCH 8
#define CDIM 192
#define C3 576
#define HEADS 8
#define CHH 24
#define NPIX 16384
#define IMW 128

// Scratch (device globals: allocation-free rule)
__device__ float g_qkv1[BATCH * C3 * NPIX];   // after 1x1 conv
__device__ float g_qkv2[BATCH * C3 * NPIX];   // after depthwise conv
__device__ float g_gram[BATCH * HEADS * CHH * CHH];
__device__ float g_nq[BATCH * CDIM];
__device__ float g_nk[BATCH * CDIM];
__device__ float g_weff[BATCH * CDIM * CDIM];

// ---------------------------------------------------------------------------
// Generic C[o,n] = sum_c W[o,c] * X[c,n] per batch. 64x64 tile, 256 threads,
// each thread 4(o) x 4(n) micro-tile. n is the fast (coalesced) axis.
// ---------------------------------------------------------------------------
__global__ void gemm_cn(const float* __restrict__ Wbase, long long wstride,
                        const float* __restrict__ Xbase, long long xstride,
                        float* __restrict__ Ybase, long long ystride,
                        int Cin)
{
    const int b = blockIdx.z;
    const float* Wp = Wbase + (long long)b * wstride;
    const float* Xp = Xbase + (long long)b * xstride;
    float* Yp = Ybase + (long long)b * ystride;

    const int o0 = blockIdx.y * 64;
    const int n0 = blockIdx.x * 64;

    __shared__ float Ws[64][17];     // padded: conflict-free broadcast reads
    __shared__ float Xs[16][64];     // float4 reads, conflict-free

    const int tid = threadIdx.x;           // 256
    const int tx = tid & 15;               // n group
    const int ty = tid >> 4;               // o group

    float acc[4][4];
#pragma unroll
    for (int i = 0; i < 4; ++i)
#pragma unroll
        for (int j = 0; j < 4; ++j) acc[i][j] = 0.f;

    for (int k0 = 0; k0 < Cin; k0 += 16) {
        // load W tile: 64 x 16
#pragma unroll
        for (int e = tid; e < 1024; e += 256) {
            int o = e >> 4, k = e & 15;
            Ws[o][k] = Wp[(o0 + o) * Cin + k0 + k];
        }
        // load X tile: 16 x 64 (rows contiguous in n)
#pragma unroll
        for (int e = tid; e < 1024; e += 256) {
            int k = e >> 6, n = e & 63;
            Xs[k][n] = Xp[(long long)(k0 + k) * NPIX + n0 + n];
        }
        __syncthreads();
#pragma unroll
        for (int k = 0; k < 16; ++k) {
            float wv[4];
#pragma unroll
            for (int i = 0; i < 4; ++i) wv[i] = Ws[ty + 16 * i][k];
            float4 xv = *reinterpret_cast<const float4*>(&Xs[k][tx * 4]);
            float xs[4] = {xv.x, xv.y, xv.z, xv.w};
#pragma unroll
            for (int i = 0; i < 4; ++i)
#pragma unroll
                for (int j = 0; j < 4; ++j) acc[i][j] += wv[i] * xs[j];
        }
        __syncthreads();
    }

#pragma unroll
    for (int i = 0; i < 4; ++i) {
        float4 r = make_float4(acc[i][0], acc[i][1], acc[i][2], acc[i][3]);
        *reinterpret_cast<float4*>(
            &Yp[(long long)(o0 + ty + 16 * i) * NPIX + n0 + tx * 4]) = r;
    }
}

// ---------------------------------------------------------------------------
// 3x3 depthwise conv, padding 1 (cross-correlation, matching lax.conv)
// ---------------------------------------------------------------------------
__global__ void dwconv_kernel(const float* __restrict__ in,
                              const float* __restrict__ wdw,
                              float* __restrict__ out)
{
    long long idx = (long long)blockIdx.x * blockDim.x + threadIdx.x;
    if (idx >= (long long)BATCH * C3 * NPIX) return;
    int n = (int)(idx & (NPIX - 1));
    int ch = (int)(idx >> 14);          // b*576 + oc
    int oc = ch % C3;
    int y = n >> 7, x = n & 127;
    const float* w = wdw + oc * 9;
    const float* p = in + (long long)ch * NPIX;
    float accv = 0.f;
#pragma unroll
    for (int dy = -1; dy <= 1; ++dy) {
        int yy = y + dy;
        if (yy < 0 || yy > IMW - 1) continue;
#pragma unroll
        for (int dx = -1; dx <= 1; ++dx) {
            int xx = x + dx;
            if (xx < 0 || xx > IMW - 1) continue;
            accv += w[(dy + 1) * 3 + (dx + 1)] * p[yy * IMW + xx];
        }
    }
    out[idx] = accv;
}

__global__ void zero_gram_kernel()
{
    int i = blockIdx.x * blockDim.x + threadIdx.x;
    if (i < BATCH * HEADS * CHH * CHH) g_gram[i] = 0.f;
}

// ---------------------------------------------------------------------------
// Gram matrix: G[b,h,i,j] = sum_n (q*f)_i (k*f)_j.
// grid: (16 n-chunks, 64 b*h). 256 threads = 4 groups x 64; each group owns a
// 64-wide n slice; 8x8 thread layout, 3x3 micro-tile per thread (24 = 8*3).
// Rotated smem reads (nn = (it+l)&63) => conflict-free.
// ---------------------------------------------------------------------------
__global__ void gram_kernel(const float* __restrict__ feat)
{
    __shared__ float QF[4][CHH][64];
    __shared__ float KF[4][CHH][64];

    const int bh = blockIdx.y;            // b*8 + hd
    const int b = bh >> 3, hd = bh & 7;
    const int n0 = blockIdx.x * 1024;
    const int t = threadIdx.x;
    const int g = t >> 6, l = t & 63;
    const int li = l >> 3, lj = l & 7;
    const int i0 = li * 3, j0 = lj * 3;

    const float* qbase = g_qkv2 + ((long long)b * C3 + hd * CHH) * NPIX;
    const float* kbase = g_qkv2 + ((long long)b * C3 + CDIM + hd * CHH) * NPIX;
    const float* fbase = feat + ((long long)b * CDIM + hd * CHH) * NPIX;

    float acc[3][3];
#pragma unroll
    for (int a = 0; a < 3; ++a)
#pragma unroll
        for (int c = 0; c < 3; ++c) acc[a][c] = 0.f;

    for (int s = 0; s < 1024; s += 256) {
        const int nb = n0 + s + g * 64;
        for (int e = l; e < CHH * 64; e += 64) {
            int i = e >> 6, nn = e & 63;
            long long off = (long long)i * NPIX + nb + nn;
            float fv = fbase[off];
            QF[g][i][nn] = qbase[off] * fv;
            KF[g][i][nn] = kbase[off] * fv;
        }
        __syncthreads();
#pragma unroll 4
        for (int it = 0; it < 64; ++it) {
            int nn = (it + l) & 63;
            float q0 = QF[g][i0 + 0][nn];
            float q1 = QF[g][i0 + 1][nn];
            float q2 = QF[g][i0 + 2][nn];
            float k0 = KF[g][j0 + 0][nn];
            float k1 = KF[g][j0 + 1][nn];
            float k2 = KF[g][j0 + 2][nn];
            acc[0][0] += q0 * k0; acc[0][1] += q0 * k1; acc[0][2] += q0 * k2;
            acc[1][0] += q1 * k0; acc[1][1] += q1 * k1; acc[1][2] += q1 * k2;
            acc[2][0] += q2 * k0; acc[2][1] += q2 * k1; acc[2][2] += q2 * k2;
        }
        __syncthreads();
    }

#pragma unroll
    for (int a = 0; a < 3; ++a)
#pragma unroll
        for (int c = 0; c < 3; ++c)
            atomicAdd(&g_gram[(bh * CHH + i0 + a) * CHH + j0 + c], acc[a][c]);
}

// ---------------------------------------------------------------------------
// Squared norms of q*f and k*f per (b, channel). One block per (b, ch, q/k).
// ---------------------------------------------------------------------------
__global__ void norm_kernel(const float* __restrict__ feat)
{
    const int b = blockIdx.y;
    const int tchan = blockIdx.x;         // 0..383
    const int isK = tchan >= CDIM;
    const int c = isK ? tchan - CDIM : tchan;
    const int qkvch = isK ? CDIM + c : c;
    const float* p = g_qkv2 + ((long long)b * C3 + qkvch) * NPIX;
    const float* f = feat + ((long long)b * CDIM + c) * NPIX;

    float s = 0.f;
    for (int n = threadIdx.x; n < NPIX; n += 256) {
        float v = p[n] * f[n];
        s += v * v;
    }
    __shared__ float red[8];
#pragma unroll
    for (int off = 16; off; off >>= 1) s += __shfl_down_sync(0xffffffffu, s, off);
    if ((threadIdx.x & 31) == 0) red[threadIdx.x >> 5] = s;
    __syncthreads();
    if (threadIdx.x < 8) {
        s = red[threadIdx.x];
#pragma unroll
        for (int off = 4; off; off >>= 1) s += __shfl_down_sync(0xffu, s, off);
        if (threadIdx.x == 0) {
            if (isK) g_nk[b * CDIM + c] = s;
            else     g_nq[b * CDIM + c] = s;
        }
    }
}

// ---------------------------------------------------------------------------
// Per-batch: normalize Gram, softmax rows, combine with W_proj into W_eff:
//   W_eff[o, hd*24+j] = sum_i W_proj[o, hd*24+i] * A[hd][i][j]
// One block per batch, 384 threads.
// ---------------------------------------------------------------------------
__global__ void softmax_weff_kernel(const float* __restrict__ temp,
                                    const float* __restrict__ Wp)
{
    const int b = blockIdx.x;
    const int t = threadIdx.x;            // 384
    __shared__ float A[HEADS][CHH][CHH];
    __shared__ float qinv[CDIM], kinv[CDIM];

    if (t < CDIM) {
        float s = sqrtf(g_nq[b * CDIM + t]);
        qinv[t] = 1.0f / fmaxf(s, 1e-12f);
    } else if (t < 2 * CDIM) {
        int c = t - CDIM;
        float s = sqrtf(g_nk[b * CDIM + c]);
        kinv[c] = 1.0f / fmaxf(s, 1e-12f);
    }
    __syncthreads();

    if (t < CDIM) {
        const int hd = t / CHH, i = t % CHH;
        const float tp = temp[hd];
        const float qi = qinv[hd * CHH + i];
        float row[CHH];
        float m = -1e30f;
#pragma unroll
        for (int j = 0; j < CHH; ++j) {
            float v = g_gram[((b * HEADS + hd) * CHH + i) * CHH + j]
                      * tp * qi * kinv[hd * CHH + j];
            row[j] = v;
            m = fmaxf(m, v);
        }
        float ssum = 0.f;
#pragma unroll
        for (int j = 0; j < CHH; ++j) { row[j] = __expf(row[j] - m); ssum += row[j]; }
        // use expf (accurate) instead of fast path to stay close to reference
        ssum = 0.f;
#pragma unroll
        for (int j = 0; j < CHH; ++j) {
            row[j] = expf(fminf(g_gram[((b * HEADS + hd) * CHH + i) * CHH + j]
                                * tp * qi * kinv[hd * CHH + j] - m, 80.f));
            ssum += row[j];
        }
        float inv = 1.0f / ssum;
#pragma unroll
        for (int j = 0; j < CHH; ++j) A[hd][i][j] = row[j] * inv;
    }
    __syncthreads();

    for (int idx = t; idx < CDIM * CDIM; idx += 384) {
        const int o = idx / CDIM, cc = idx % CDIM;
        const int hd = cc / CHH, j = cc % CHH;
        float s = 0.f;
#pragma unroll
        for (int i = 0; i < CHH; ++i)
            s += Wp[o * CDIM + hd * CHH + i] * A[hd][i][j];
        g_weff[(long long)b * CDIM * CDIM + idx] = s;
    }
}

// ---------------------------------------------------------------------------
extern "C" void kernel_launch(void* const* d_in, const int* in_sizes, int n_in,
                              void* d_out, int out_size)
{
    (void)in_sizes; (void)n_in; (void)out_size;
    const float* x     = (const float*)d_in[0];
    const float* feat  = (const float*)d_in[1];
    const float* Wqkv  = (const float*)d_in[2];
    const float* Wdw   = (const float*)d_in[3];
    const float* Wproj = (const float*)d_in[4];
    const float* temp  = (const float*)d_in[5];
    float* out = (float*)d_out;

    float *qkv1, *qkv2, *weff;
    cudaGetSymbolAddress((void**)&qkv1, g_qkv1);
    cudaGetSymbolAddress((void**)&qkv2, g_qkv2);
    cudaGetSymbolAddress((void**)&weff, g_weff);

    // 1) qkv = W_qkv @ x : [576,192] x [192,16384] per batch
    gemm_cn<<<dim3(NPIX / 64, C3 / 64, BATCH), 256>>>(
        Wqkv, 0LL, x, (long long)CDIM * NPIX, qkv1, (long long)C3 * NPIX, CDIM);

    // 2) 3x3 depthwise conv
    {
        long long total = (long long)BATCH * C3 * NPIX;
        int blocks = (int)((total + 255) / 256);
        dwconv_kernel<<<blocks, 256>>>(qkv1, Wdw, qkv2);
    }

    // 3) Gram + norms
    zero_gram_kernel<<<(BATCH * HEADS * CHH * CHH + 255) / 256, 256>>>();
    gram_kernel<<<dim3(16, BATCH * HEADS), 256>>>(feat);
    norm_kernel<<<dim3(2 * CDIM, BATCH), 256>>>(feat);

    // 4) softmax + W_eff = W_proj @ A_blockdiag
    softmax_weff_kernel<<<BATCH, 384>>>(temp, Wproj);

    // 5) y = W_eff @ v : [192,192] x [192,16384] per batch
    gemm_cn<<<dim3(NPIX / 64, CDIM / 64, BATCH), 256>>>(
        weff, (long long)CDIM * CDIM,
        qkv2 + (long long)2 * CDIM * NPIX, (long long)C3 * NPIX,
        out, (long long)CDIM * NPIX, CDIM);
}

// round 3
// speedup vs baseline: 2.0563x; 2.0563x over previous
#include <cuda_runtime.h>
#include <cuda_bf16.h>
#include <math.h>
#include <stdint.h>

#define BATCH 8
#define CDIM 192
#define C3 576
#define HEADS 8
#define CHH 24
#define NPIX 16384
#define IMW 128

// ---------------- scratch (device globals; allocation-free rule) ------------
__device__ float g_qkv1[BATCH * C3 * NPIX];
__device__ float g_qkv2[BATCH * C3 * NPIX];
__device__ float g_gram[BATCH * HEADS * CHH * CHH];
__device__ float g_nq[BATCH * CDIM];
__device__ float g_nk[BATCH * CDIM];
__device__ __nv_bfloat16 g_wq_hi[C3 * CDIM];
__device__ __nv_bfloat16 g_wq_lo[C3 * CDIM];
__device__ __nv_bfloat16 g_weff_hi[BATCH * CDIM * CDIM];
__device__ __nv_bfloat16 g_weff_lo[BATCH * CDIM * CDIM];

#define MMA_BF16(d, a, bb) \
    asm volatile("mma.sync.aligned.m16n8k16.row.col.f32.bf16.bf16.f32 " \
        "{%0,%1,%2,%3}, {%4,%5,%6,%7}, {%8,%9}, {%0,%1,%2,%3};" \
        : "+f"((d)[0]), "+f"((d)[1]), "+f"((d)[2]), "+f"((d)[3]) \
        : "r"((a)[0]), "r"((a)[1]), "r"((a)[2]), "r"((a)[3]), \
          "r"((bb)[0]), "r"((bb)[1]))

__device__ __forceinline__ uint32_t pack_bf2(__nv_bfloat16 lo16, __nv_bfloat16 hi16) {
    return ((uint32_t)__bfloat16_as_ushort(hi16) << 16) | __bfloat16_as_ushort(lo16);
}

// ---------------------------------------------------------------------------
// HMMA GEMM: Y[o,n] = sum_c W[o,c] X[c,n] per batch. bf16 hi/lo 3-pass.
// BM=192, BN=128, BK=32, 256 threads (8 warps: 4 in M x 2 in N; 48x64/warp).
// ---------------------------------------------------------------------------
#define LDA 36
#define LDB 40

__global__ __launch_bounds__(256, 1)
void gemm_mma(const __nv_bfloat16* __restrict__ Whi,
              const __nv_bfloat16* __restrict__ Wlo,
              long long wstride,
              const float* __restrict__ X, long long xstride,
              float* __restrict__ Y, long long ystride)
{
    const int b = blockIdx.z;
    const int o0 = blockIdx.x * 192;
    const int n0 = blockIdx.y * 128;
    const uint32_t* Wh32 = reinterpret_cast<const uint32_t*>(Whi + (long long)b * wstride);
    const uint32_t* Wl32 = reinterpret_cast<const uint32_t*>(Wlo + (long long)b * wstride);
    const float* Xp = X + (long long)b * xstride;
    float* Yp = Y + (long long)b * ystride;

    __shared__ __nv_bfloat16 Ah[192 * LDA];
    __shared__ __nv_bfloat16 Al[192 * LDA];
    __shared__ __nv_bfloat16 Bh[128 * LDB];
    __shared__ __nv_bfloat16 Bl[128 * LDB];

    const int tid = threadIdx.x;
    const int lane = tid & 31;
    const int wid = tid >> 5;
    const int wm = wid & 3;            // 0..3 -> rows wm*48
    const int wn = wid >> 2;           // 0..1 -> cols wn*64

    float acc[3][8][4];
#pragma unroll
    for (int mi = 0; mi < 3; ++mi)
#pragma unroll
        for (int ni = 0; ni < 8; ++ni)
#pragma unroll
            for (int q = 0; q < 4; ++q) acc[mi][ni][q] = 0.f;

    // B prefetch registers (8 u32 pairs per buffer per thread)
    float pb0[8], pb1[8];
    const int bn = tid & 127;                     // n within tile
    const int bkbase = (tid >> 7) * 2;            // 0 or 2

#pragma unroll
    for (int j = 0; j < 8; ++j) {
        int kp = j * 2 + (tid >> 7);              // 0..15
        pb0[j] = Xp[(long long)(2 * kp) * NPIX + n0 + bn];
        pb1[j] = Xp[(long long)(2 * kp + 1) * NPIX + n0 + bn];
    }
    (void)bkbase;

    for (int kt = 0; kt < 6; ++kt) {
        // ---- store phase: A (global->smem), B (regs->cvt->smem) ----
#pragma unroll
        for (int j = 0; j < 12; ++j) {
            int e = j * 256 + tid;                // 0..3071
            int row = e >> 4, col = e & 15;       // col: u32 index (2 bf16)
            uint32_t vh = Wh32[(o0 + row) * 96 + kt * 16 + col];
            uint32_t vl = Wl32[(o0 + row) * 96 + kt * 16 + col];
            *reinterpret_cast<uint32_t*>(&Ah[row * LDA + col * 2]) = vh;
            *reinterpret_cast<uint32_t*>(&Al[row * LDA + col * 2]) = vl;
        }
#pragma unroll
        for (int j = 0; j < 8; ++j) {
            int kp = j * 2 + (tid >> 7);
            float v0 = pb0[j], v1 = pb1[j];
            __nv_bfloat16 h0 = __float2bfloat16(v0);
            __nv_bfloat16 h1 = __float2bfloat16(v1);
            __nv_bfloat16 l0 = __float2bfloat16(v0 - __bfloat162float(h0));
            __nv_bfloat16 l1 = __float2bfloat16(v1 - __bfloat162float(h1));
            *reinterpret_cast<uint32_t*>(&Bh[bn * LDB + kp * 2]) = pack_bf2(h0, h1);
            *reinterpret_cast<uint32_t*>(&Bl[bn * LDB + kp * 2]) = pack_bf2(l0, l1);
        }
        __syncthreads();

        // ---- prefetch next B tile into regs ----
        if (kt < 5) {
#pragma unroll
            for (int j = 0; j < 8; ++j) {
                int kp = j * 2 + (tid >> 7);
                int k = (kt + 1) * 32 + 2 * kp;
                pb0[j] = Xp[(long long)k * NPIX + n0 + bn];
                pb1[j] = Xp[(long long)(k + 1) * NPIX + n0 + bn];
            }
        }

        // ---- compute: 2 k-steps of 16 ----
#pragma unroll
        for (int ks = 0; ks < 2; ++ks) {
            const int ccol = ks * 16 + (lane & 3) * 2;
            uint32_t fah[3][4], fal[3][4];
#pragma unroll
            for (int mi = 0; mi < 3; ++mi) {
                int rb = wm * 48 + mi * 16 + (lane >> 2);
                fah[mi][0] = *reinterpret_cast<const uint32_t*>(&Ah[rb * LDA + ccol]);
                fah[mi][1] = *reinterpret_cast<const uint32_t*>(&Ah[(rb + 8) * LDA + ccol]);
                fah[mi][2] = *reinterpret_cast<const uint32_t*>(&Ah[rb * LDA + ccol + 8]);
                fah[mi][3] = *reinterpret_cast<const uint32_t*>(&Ah[(rb + 8) * LDA + ccol + 8]);
                fal[mi][0] = *reinterpret_cast<const uint32_t*>(&Al[rb * LDA + ccol]);
                fal[mi][1] = *reinterpret_cast<const uint32_t*>(&Al[(rb + 8) * LDA + ccol]);
                fal[mi][2] = *reinterpret_cast<const uint32_t*>(&Al[rb * LDA + ccol + 8]);
                fal[mi][3] = *reinterpret_cast<const uint32_t*>(&Al[(rb + 8) * LDA + ccol + 8]);
            }
            uint32_t fbh[8][2], fbl[8][2];
#pragma unroll
            for (int ni = 0; ni < 8; ++ni) {
                int cb = wn * 64 + ni * 8 + (lane >> 2);
                fbh[ni][0] = *reinterpret_cast<const uint32_t*>(&Bh[cb * LDB + ccol]);
                fbh[ni][1] = *reinterpret_cast<const uint32_t*>(&Bh[cb * LDB + ccol + 8]);
                fbl[ni][0] = *reinterpret_cast<const uint32_t*>(&Bl[cb * LDB + ccol]);
                fbl[ni][1] = *reinterpret_cast<const uint32_t*>(&Bl[cb * LDB + ccol + 8]);
            }
#pragma unroll
            for (int mi = 0; mi < 3; ++mi)
#pragma unroll
                for (int ni = 0; ni < 8; ++ni) {
                    MMA_BF16(acc[mi][ni], fah[mi], fbh[ni]);
                    MMA_BF16(acc[mi][ni], fah[mi], fbl[ni]);
                    MMA_BF16(acc[mi][ni], fal[mi], fbh[ni]);
                }
        }
        __syncthreads();
    }

    // ---- epilogue ----
#pragma unroll
    for (int mi = 0; mi < 3; ++mi) {
        int r = o0 + wm * 48 + mi * 16 + (lane >> 2);
#pragma unroll
        for (int ni = 0; ni < 8; ++ni) {
            int c = n0 + wn * 64 + ni * 8 + (lane & 3) * 2;
            *reinterpret_cast<float2*>(&Yp[(long long)r * NPIX + c]) =
                make_float2(acc[mi][ni][0], acc[mi][ni][1]);
            *reinterpret_cast<float2*>(&Yp[(long long)(r + 8) * NPIX + c]) =
                make_float2(acc[mi][ni][2], acc[mi][ni][3]);
        }
    }
}

// ---------------------------------------------------------------------------
// Weight prep: fp32 -> bf16 hi/lo
// ---------------------------------------------------------------------------
__global__ void prep_wqkv_kernel(const float* __restrict__ W)
{
    int idx = blockIdx.x * blockDim.x + threadIdx.x;
    if (idx >= C3 * CDIM) return;
    float v = W[idx];
    __nv_bfloat16 h = __float2bfloat16(v);
    g_wq_hi[idx] = h;
    g_wq_lo[idx] = __float2bfloat16(v - __bfloat162float(h));
}

// ---------------------------------------------------------------------------
// 3x3 depthwise conv, padding 1
// ---------------------------------------------------------------------------
__global__ void dwconv_kernel(const float* __restrict__ in,
                              const float* __restrict__ wdw,
                              float* __restrict__ out)
{
    long long idx = (long long)blockIdx.x * blockDim.x + threadIdx.x;
    if (idx >= (long long)BATCH * C3 * NPIX) return;
    int n = (int)(idx & (NPIX - 1));
    int ch = (int)(idx >> 14);
    int oc = ch % C3;
    int y = n >> 7, x = n & 127;
    const float* w = wdw + oc * 9;
    const float* p = in + (long long)ch * NPIX;
    float accv = 0.f;
#pragma unroll
    for (int dy = -1; dy <= 1; ++dy) {
        int yy = y + dy;
        if (yy < 0 || yy > IMW - 1) continue;
#pragma unroll
        for (int dx = -1; dx <= 1; ++dx) {
            int xx = x + dx;
            if (xx < 0 || xx > IMW - 1) continue;
            accv += w[(dy + 1) * 3 + (dx + 1)] * p[yy * IMW + xx];
        }
    }
    out[idx] = accv;
}

__global__ void zero_misc_kernel()
{
    int i = blockIdx.x * blockDim.x + threadIdx.x;
    if (i < BATCH * HEADS * CHH * CHH) g_gram[i] = 0.f;
    if (i < BATCH * CDIM) { g_nq[i] = 0.f; g_nk[i] = 0.f; }
}

// ---------------------------------------------------------------------------
// Gram + fused norms
// ---------------------------------------------------------------------------
__global__ void gram_kernel(const float* __restrict__ feat)
{
    __shared__ float QF[4][CHH][64];
    __shared__ float KF[4][CHH][64];

    const int bh = blockIdx.y;
    const int b = bh >> 3, hd = bh & 7;
    const int n0 = blockIdx.x * 1024;
    const int t = threadIdx.x;
    const int g = t >> 6, l = t & 63;
    const int li = l >> 3, lj = l & 7;
    const int i0 = li * 3, j0 = lj * 3;

    const float* qbase = g_qkv2 + ((long long)b * C3 + hd * CHH) * NPIX;
    const float* kbase = g_qkv2 + ((long long)b * C3 + CDIM + hd * CHH) * NPIX;
    const float* fbase = feat + ((long long)b * CDIM + hd * CHH) * NPIX;

    float acc[3][3];
#pragma unroll
    for (int a = 0; a < 3; ++a)
#pragma unroll
        for (int cc = 0; cc < 3; ++cc) acc[a][cc] = 0.f;
    float nqp = 0.f, nkp = 0.f;

    for (int s = 0; s < 1024; s += 256) {
        const int nb = n0 + s + g * 64;
        for (int e = l; e < CHH * 64; e += 64) {
            int i = e >> 6, nn = e & 63;
            long long off = (long long)i * NPIX + nb + nn;
            float fv = fbase[off];
            QF[g][i][nn] = qbase[off] * fv;
            KF[g][i][nn] = kbase[off] * fv;
        }
        __syncthreads();
#pragma unroll 4
        for (int it = 0; it < 64; ++it) {
            int nn = (it + l) & 63;
            float q0 = QF[g][i0 + 0][nn];
            float q1 = QF[g][i0 + 1][nn];
            float q2 = QF[g][i0 + 2][nn];
            float k0 = KF[g][j0 + 0][nn];
            float k1 = KF[g][j0 + 1][nn];
            float k2 = KF[g][j0 + 2][nn];
            acc[0][0] += q0 * k0; acc[0][1] += q0 * k1; acc[0][2] += q0 * k2;
            acc[1][0] += q1 * k0; acc[1][1] += q1 * k1; acc[1][2] += q1 * k2;
            acc[2][0] += q2 * k0; acc[2][1] += q2 * k1; acc[2][2] += q2 * k2;
        }
        if (l < CHH) {
#pragma unroll 4
            for (int it = 0; it < 64; ++it) {
                int nn = (it + l) & 63;
                float qv = QF[g][l][nn]; nqp += qv * qv;
                float kv = KF[g][l][nn]; nkp += kv * kv;
            }
        }
        __syncthreads();
    }

#pragma unroll
    for (int a = 0; a < 3; ++a)
#pragma unroll
        for (int cc = 0; cc < 3; ++cc)
            atomicAdd(&g_gram[(bh * CHH + i0 + a) * CHH + j0 + cc], acc[a][cc]);
    if (l < CHH) {
        atomicAdd(&g_nq[b * CDIM + hd * CHH + l], nqp);
        atomicAdd(&g_nk[b * CDIM + hd * CHH + l], nkp);
    }
}

// ---------------------------------------------------------------------------
// Softmax + W_eff = W_proj @ A_blockdiag, emitted bf16 hi/lo [192][192]
// ---------------------------------------------------------------------------
__global__ void softmax_weff_kernel(const float* __restrict__ temp,
                                    const float* __restrict__ Wp)
{
    const int b = blockIdx.x;
    const int t = threadIdx.x;            // 384
    __shared__ float A[HEADS][CHH][CHH];
    __shared__ float qinv[CDIM], kinv[CDIM];

    if (t < CDIM) {
        qinv[t] = 1.0f / fmaxf(sqrtf(g_nq[b * CDIM + t]), 1e-12f);
    } else if (t < 2 * CDIM) {
        int c = t - CDIM;
        kinv[c] = 1.0f / fmaxf(sqrtf(g_nk[b * CDIM + c]), 1e-12f);
    }
    __syncthreads();

    if (t < CDIM) {
        const int hd = t / CHH, i = t % CHH;
        const float tp = temp[hd];
        const float qi = qinv[hd * CHH + i];
        float row[CHH];
        float m = -1e30f;
#pragma unroll
        for (int j = 0; j < CHH; ++j) {
            float v = g_gram[((b * HEADS + hd) * CHH + i) * CHH + j]
                      * tp * qi * kinv[hd * CHH + j];
            row[j] = v;
            m = fmaxf(m, v);
        }
        float ssum = 0.f;
#pragma unroll
        for (int j = 0; j < CHH; ++j) { row[j] = expf(row[j] - m); ssum += row[j]; }
        float inv = 1.0f / ssum;
#pragma unroll
        for (int j = 0; j < CHH; ++j) A[hd][i][j] = row[j] * inv;
    }
    __syncthreads();

    for (int idx = t; idx < CDIM * CDIM; idx += 384) {
        const int o = idx / CDIM, cc = idx % CDIM;
        const int hd = cc / CHH, j = cc % CHH;
        float s = 0.f;
#pragma unroll
        for (int i = 0; i < CHH; ++i)
            s += Wp[o * CDIM + hd * CHH + i] * A[hd][i][j];
        __nv_bfloat16 h = __float2bfloat16(s);
        g_weff_hi[(long long)b * CDIM * CDIM + idx] = h;
        g_weff_lo[(long long)b * CDIM * CDIM + idx] =
            __float2bfloat16(s - __bfloat162float(h));
    }
}

// ---------------------------------------------------------------------------
extern "C" void kernel_launch(void* const* d_in, const int* in_sizes, int n_in,
                              void* d_out, int out_size)
{
    (void)in_sizes; (void)n_in; (void)out_size;
    const float* x     = (const float*)d_in[0];
    const float* feat  = (const float*)d_in[1];
    const float* Wqkv  = (const float*)d_in[2];
    const float* Wdw   = (const float*)d_in[3];
    const float* Wproj = (const float*)d_in[4];
    const float* temp  = (const float*)d_in[5];
    float* out = (float*)d_out;

    float *qkv1, *qkv2;
    __nv_bfloat16 *wqh, *wql, *wfh, *wfl;
    cudaGetSymbolAddress((void**)&qkv1, g_qkv1);
    cudaGetSymbolAddress((void**)&qkv2, g_qkv2);
    cudaGetSymbolAddress((void**)&wqh, g_wq_hi);
    cudaGetSymbolAddress((void**)&wql, g_wq_lo);
    cudaGetSymbolAddress((void**)&wfh, g_weff_hi);
    cudaGetSymbolAddress((void**)&wfl, g_weff_lo);

    // 0) split W_qkv to bf16 hi/lo
    prep_wqkv_kernel<<<(C3 * CDIM + 255) / 256, 256>>>(Wqkv);

    // 1) qkv1 = W_qkv @ x  (HMMA)
    gemm_mma<<<dim3(3, NPIX / 128, BATCH), 256>>>(
        wqh, wql, 0LL, x, (long long)CDIM * NPIX, qkv1, (long long)C3 * NPIX);

    // 2) 3x3 depthwise conv
    {
        long long total = (long long)BATCH * C3 * NPIX;
        dwconv_kernel<<<(int)((total + 255) / 256), 256>>>(qkv1, Wdw, qkv2);
    }

    // 3) Gram + norms (fused)
    zero_misc_kernel<<<(BATCH * HEADS * CHH * CHH + 255) / 256, 256>>>();
    gram_kernel<<<dim3(16, BATCH * HEADS), 256>>>(feat);

    // 4) softmax + W_eff (bf16 hi/lo)
    softmax_weff_kernel<<<BATCH, 384>>>(temp, Wproj);

    // 5) out = W_eff @ v  (HMMA)
    gemm_mma<<<dim3(1, NPIX / 128, BATCH), 256>>>(
        wfh, wfl, (long long)CDIM * CDIM,
        qkv2 + (long long)2 * CDIM * NPIX, (long long)C3 * NPIX,
        out, (long long)CDIM * NPIX);
}

// round 4
// speedup vs baseline: 2.2965x; 1.1168x over previous
#include <cuda_runtime.h>
#include <cuda_bf16.h>
#include <math.h>
#include <stdint.h>

#define BATCH 8
#define CDIM 192
#define C3 576
#define HEADS 8
#define CHH 24
#define NPIX 16384
#define IMW 128

// ---------------- scratch (device globals; allocation-free rule) ------------
__device__ float g_qkv1[BATCH * C3 * NPIX];
__device__ float g_qkv2[BATCH * C3 * NPIX];
__device__ float g_gram[BATCH * HEADS * CHH * CHH];
__device__ float g_nq[BATCH * CDIM];
__device__ float g_nk[BATCH * CDIM];
__device__ __nv_bfloat16 g_wq_hi[C3 * CDIM];
__device__ __nv_bfloat16 g_wq_lo[C3 * CDIM];
__device__ __nv_bfloat16 g_weff_hi[BATCH * CDIM * CDIM];
__device__ __nv_bfloat16 g_weff_lo[BATCH * CDIM * CDIM];

#define MMA_BF16(d, a, bb) \
    asm volatile("mma.sync.aligned.m16n8k16.row.col.f32.bf16.bf16.f32 " \
        "{%0,%1,%2,%3}, {%4,%5,%6,%7}, {%8,%9}, {%0,%1,%2,%3};" \
        : "+f"((d)[0]), "+f"((d)[1]), "+f"((d)[2]), "+f"((d)[3]) \
        : "r"((a)[0]), "r"((a)[1]), "r"((a)[2]), "r"((a)[3]), \
          "r"((bb)[0]), "r"((bb)[1]))

__device__ __forceinline__ uint32_t pack_bf2(__nv_bfloat16 lo16, __nv_bfloat16 hi16) {
    return ((uint32_t)__bfloat16_as_ushort(hi16) << 16) | __bfloat16_as_ushort(lo16);
}
__device__ __forceinline__ uint32_t smem_u32(const void* p) {
    uint32_t a;
    asm("{ .reg .u64 t; cvta.to.shared.u64 t, %1; cvt.u32.u64 %0, t; }"
        : "=r"(a) : "l"(p));
    return a;
}
__device__ __forceinline__ void cp_async16(uint32_t dst, const void* src) {
    asm volatile("cp.async.cg.shared.global [%0], [%1], 16;" :: "r"(dst), "l"(src));
}

// ---------------------------------------------------------------------------
// HMMA GEMM: Y[o,n] = sum_c W[o,c] X[c,n] per batch. bf16 hi/lo 3-pass.
// BM=192, BN=128, BK=32, K=192. 256 threads (8 warps: 4M x 2N; 48x64/warp).
// Full A (hi/lo) loaded once into dynamic SMEM via cp.async; B register-
// prefetched (LDG.128) and converted fp32->bf16 hi/lo per tile.
// ---------------------------------------------------------------------------
#define LDAE 200          // A row stride in bf16 elems (192 + 8 pad; 400B, 16B-aligned)
#define LDB  40           // B row stride in bf16 elems (80B, 16B-aligned)
#define SMEM_GEMM ((2 * 192 * LDAE + 2 * 128 * LDB) * 2)   // 174080 bytes

__global__ __launch_bounds__(256, 1)
void gemm_mma(const __nv_bfloat16* __restrict__ Whi,
              const __nv_bfloat16* __restrict__ Wlo,
              long long wstride,
              const float* __restrict__ X, long long xstride,
              float* __restrict__ Y, long long ystride)
{
    extern __shared__ __nv_bfloat16 smem[];
    __nv_bfloat16* Ah = smem;
    __nv_bfloat16* Al = Ah + 192 * LDAE;
    __nv_bfloat16* Bh = Al + 192 * LDAE;
    __nv_bfloat16* Bl = Bh + 128 * LDB;

    const int b = blockIdx.z;
    const int o0 = blockIdx.x * 192;
    const int n0 = blockIdx.y * 128;
    const __nv_bfloat16* Wh = Whi + (long long)b * wstride;
    const __nv_bfloat16* Wl = Wlo + (long long)b * wstride;
    const float* Xp = X + (long long)b * xstride;
    float* Yp = Y + (long long)b * ystride;

    const int tid = threadIdx.x;
    const int lane = tid & 31;
    const int wid = tid >> 5;
    const int wm = wid & 3;
    const int wn = wid >> 2;

    // ---- async load of full A (hi + lo): 192 rows x 192 k, 16B chunks ----
    {
        const uint32_t ah = smem_u32(Ah), al = smem_u32(Al);
#pragma unroll
        for (int c = 0; c < 18; ++c) {
            int ch = c * 256 + tid;            // 0..4607
            int row = ch / 24, col = ch % 24;  // col: 16B chunk (8 bf16)
            uint32_t doff = (uint32_t)(row * LDAE + col * 8) * 2u;
            long long soff = (long long)(o0 + row) * CDIM + col * 8;
            cp_async16(ah + doff, Wh + soff);
            cp_async16(al + doff, Wl + soff);
        }
        asm volatile("cp.async.commit_group;");
    }

    float acc[3][8][4];
#pragma unroll
    for (int mi = 0; mi < 3; ++mi)
#pragma unroll
        for (int ni = 0; ni < 8; ++ni)
#pragma unroll
            for (int q = 0; q < 4; ++q) acc[mi][ni][q] = 0.f;

    // ---- B prefetch regs: thread covers rows {kr, kr+1} x (j*16) and 4 n's ----
    const int kr = (tid >> 5) * 2;        // 0..14 even
    const int nc = (tid & 31) * 4;        // n within tile
    float4 pb[2][2];
#pragma unroll
    for (int j = 0; j < 2; ++j)
#pragma unroll
        for (int r = 0; r < 2; ++r)
            pb[j][r] = *reinterpret_cast<const float4*>(
                &Xp[(long long)(j * 16 + kr + r) * NPIX + n0 + nc]);

    asm volatile("cp.async.wait_group 0;");
    __syncthreads();

    for (int kt = 0; kt < 6; ++kt) {
        // ---- store B tile: cvt fp32 -> hi/lo bf16 pairs (k-pairs packed) ----
#pragma unroll
        for (int j = 0; j < 2; ++j) {
            const int kk = j * 16 + kr;   // even k in tile
            float e0[4] = {pb[j][0].x, pb[j][0].y, pb[j][0].z, pb[j][0].w};
            float e1[4] = {pb[j][1].x, pb[j][1].y, pb[j][1].z, pb[j][1].w};
#pragma unroll
            for (int i = 0; i < 4; ++i) {
                __nv_bfloat16 h0 = __float2bfloat16(e0[i]);
                __nv_bfloat16 h1 = __float2bfloat16(e1[i]);
                __nv_bfloat16 l0 = __float2bfloat16(e0[i] - __bfloat162float(h0));
                __nv_bfloat16 l1 = __float2bfloat16(e1[i] - __bfloat162float(h1));
                *reinterpret_cast<uint32_t*>(&Bh[(nc + i) * LDB + kk]) = pack_bf2(h0, h1);
                *reinterpret_cast<uint32_t*>(&Bl[(nc + i) * LDB + kk]) = pack_bf2(l0, l1);
            }
        }
        __syncthreads();

        // ---- prefetch next B tile (overlaps compute below) ----
        if (kt < 5) {
#pragma unroll
            for (int j = 0; j < 2; ++j)
#pragma unroll
                for (int r = 0; r < 2; ++r)
                    pb[j][r] = *reinterpret_cast<const float4*>(
                        &Xp[(long long)((kt + 1) * 32 + j * 16 + kr + r) * NPIX + n0 + nc]);
        }

        // ---- compute: 2 k-steps of 16 ----
#pragma unroll
        for (int ks = 0; ks < 2; ++ks) {
            const int kga = kt * 32 + ks * 16 + (lane & 3) * 2;  // global k for A
            const int kb = ks * 16 + (lane & 3) * 2;             // k within tile for B
            uint32_t fah[3][4], fal[3][4];
#pragma unroll
            for (int mi = 0; mi < 3; ++mi) {
                int rb = wm * 48 + mi * 16 + (lane >> 2);
                fah[mi][0] = *reinterpret_cast<const uint32_t*>(&Ah[rb * LDAE + kga]);
                fah[mi][1] = *reinterpret_cast<const uint32_t*>(&Ah[(rb + 8) * LDAE + kga]);
                fah[mi][2] = *reinterpret_cast<const uint32_t*>(&Ah[rb * LDAE + kga + 8]);
                fah[mi][3] = *reinterpret_cast<const uint32_t*>(&Ah[(rb + 8) * LDAE + kga + 8]);
                fal[mi][0] = *reinterpret_cast<const uint32_t*>(&Al[rb * LDAE + kga]);
                fal[mi][1] = *reinterpret_cast<const uint32_t*>(&Al[(rb + 8) * LDAE + kga]);
                fal[mi][2] = *reinterpret_cast<const uint32_t*>(&Al[rb * LDAE + kga + 8]);
                fal[mi][3] = *reinterpret_cast<const uint32_t*>(&Al[(rb + 8) * LDAE + kga + 8]);
            }
            uint32_t fbh[8][2], fbl[8][2];
#pragma unroll
            for (int ni = 0; ni < 8; ++ni) {
                int cb = wn * 64 + ni * 8 + (lane >> 2);
                fbh[ni][0] = *reinterpret_cast<const uint32_t*>(&Bh[cb * LDB + kb]);
                fbh[ni][1] = *reinterpret_cast<const uint32_t*>(&Bh[cb * LDB + kb + 8]);
                fbl[ni][0] = *reinterpret_cast<const uint32_t*>(&Bl[cb * LDB + kb]);
                fbl[ni][1] = *reinterpret_cast<const uint32_t*>(&Bl[cb * LDB + kb + 8]);
            }
#pragma unroll
            for (int mi = 0; mi < 3; ++mi)
#pragma unroll
                for (int ni = 0; ni < 8; ++ni) {
                    MMA_BF16(acc[mi][ni], fah[mi], fbh[ni]);
                    MMA_BF16(acc[mi][ni], fah[mi], fbl[ni]);
                    MMA_BF16(acc[mi][ni], fal[mi], fbh[ni]);
                }
        }
        __syncthreads();
    }

    // ---- epilogue ----
#pragma unroll
    for (int mi = 0; mi < 3; ++mi) {
        int r = o0 + wm * 48 + mi * 16 + (lane >> 2);
#pragma unroll
        for (int ni = 0; ni < 8; ++ni) {
            int c = n0 + wn * 64 + ni * 8 + (lane & 3) * 2;
            *reinterpret_cast<float2*>(&Yp[(long long)r * NPIX + c]) =
                make_float2(acc[mi][ni][0], acc[mi][ni][1]);
            *reinterpret_cast<float2*>(&Yp[(long long)(r + 8) * NPIX + c]) =
                make_float2(acc[mi][ni][2], acc[mi][ni][3]);
        }
    }
}

// ---------------------------------------------------------------------------
// Weight prep: fp32 -> bf16 hi/lo
// ---------------------------------------------------------------------------
__global__ void prep_wqkv_kernel(const float* __restrict__ W)
{
    int idx = blockIdx.x * blockDim.x + threadIdx.x;
    if (idx >= C3 * CDIM) return;
    float v = W[idx];
    __nv_bfloat16 h = __float2bfloat16(v);
    g_wq_hi[idx] = h;
    g_wq_lo[idx] = __float2bfloat16(v - __bfloat162float(h));
}

// ---------------------------------------------------------------------------
// 3x3 depthwise conv, padding 1; 4 pixels per thread (float4)
// ---------------------------------------------------------------------------
__global__ void dwconv_kernel(const float* __restrict__ in,
                              const float* __restrict__ wdw,
                              float* __restrict__ out)
{
    long long idx = (long long)blockIdx.x * blockDim.x + threadIdx.x;
    if (idx >= (long long)BATCH * C3 * (NPIX / 4)) return;
    const int n4 = (int)(idx & (NPIX / 4 - 1));
    const int ch = (int)(idx >> 12);
    const int oc = ch % C3;
    const int y = n4 >> 5;
    const int x0 = (n4 & 31) * 4;
    const float* w = wdw + oc * 9;
    const float* p = in + (long long)ch * NPIX;

    float4 o = make_float4(0.f, 0.f, 0.f, 0.f);
#pragma unroll
    for (int r = 0; r < 3; ++r) {
        int yy = y + r - 1;
        if (yy < 0 || yy > IMW - 1) continue;
        const float* row = p + yy * IMW;
        float4 c = *reinterpret_cast<const float4*>(&row[x0]);
        float lft = (x0 > 0) ? row[x0 - 1] : 0.f;
        float rgt = (x0 < IMW - 4) ? row[x0 + 4] : 0.f;
        float w0 = w[r * 3], w1 = w[r * 3 + 1], w2 = w[r * 3 + 2];
        o.x += w0 * lft + w1 * c.x + w2 * c.y;
        o.y += w0 * c.x + w1 * c.y + w2 * c.z;
        o.z += w0 * c.y + w1 * c.z + w2 * c.w;
        o.w += w0 * c.z + w1 * c.w + w2 * rgt;
    }
    *reinterpret_cast<float4*>(&out[(long long)ch * NPIX + y * IMW + x0]) = o;
}

__global__ void zero_misc_kernel()
{
    int i = blockIdx.x * blockDim.x + threadIdx.x;
    if (i < BATCH * HEADS * CHH * CHH) g_gram[i] = 0.f;
    if (i < BATCH * CDIM) { g_nq[i] = 0.f; g_nk[i] = 0.f; }
}

// ---------------------------------------------------------------------------
// Gram + fused norms
// ---------------------------------------------------------------------------
__global__ void gram_kernel(const float* __restrict__ feat)
{
    __shared__ float QF[4][CHH][64];
    __shared__ float KF[4][CHH][64];

    const int bh = blockIdx.y;
    const int b = bh >> 3, hd = bh & 7;
    const int n0 = blockIdx.x * 1024;
    const int t = threadIdx.x;
    const int g = t >> 6, l = t & 63;
    const int li = l >> 3, lj = l & 7;
    const int i0 = li * 3, j0 = lj * 3;

    const float* qbase = g_qkv2 + ((long long)b * C3 + hd * CHH) * NPIX;
    const float* kbase = g_qkv2 + ((long long)b * C3 + CDIM + hd * CHH) * NPIX;
    const float* fbase = feat + ((long long)b * CDIM + hd * CHH) * NPIX;

    float acc[3][3];
#pragma unroll
    for (int a = 0; a < 3; ++a)
#pragma unroll
        for (int cc = 0; cc < 3; ++cc) acc[a][cc] = 0.f;
    float nqp = 0.f, nkp = 0.f;

    for (int s = 0; s < 1024; s += 256) {
        const int nb = n0 + s + g * 64;
        for (int e = l; e < CHH * 64; e += 64) {
            int i = e >> 6, nn = e & 63;
            long long off = (long long)i * NPIX + nb + nn;
            float fv = fbase[off];
            QF[g][i][nn] = qbase[off] * fv;
            KF[g][i][nn] = kbase[off] * fv;
        }
        __syncthreads();
#pragma unroll 4
        for (int it = 0; it < 64; ++it) {
            int nn = (it + l) & 63;
            float q0 = QF[g][i0 + 0][nn];
            float q1 = QF[g][i0 + 1][nn];
            float q2 = QF[g][i0 + 2][nn];
            float k0 = KF[g][j0 + 0][nn];
            float k1 = KF[g][j0 + 1][nn];
            float k2 = KF[g][j0 + 2][nn];
            acc[0][0] += q0 * k0; acc[0][1] += q0 * k1; acc[0][2] += q0 * k2;
            acc[1][0] += q1 * k0; acc[1][1] += q1 * k1; acc[1][2] += q1 * k2;
            acc[2][0] += q2 * k0; acc[2][1] += q2 * k1; acc[2][2] += q2 * k2;
        }
        if (l < CHH) {
#pragma unroll 4
            for (int it = 0; it < 64; ++it) {
                int nn = (it + l) & 63;
                float qv = QF[g][l][nn]; nqp += qv * qv;
                float kv = KF[g][l][nn]; nkp += kv * kv;
            }
        }
        __syncthreads();
    }

#pragma unroll
    for (int a = 0; a < 3; ++a)
#pragma unroll
        for (int cc = 0; cc < 3; ++cc)
            atomicAdd(&g_gram[(bh * CHH + i0 + a) * CHH + j0 + cc], acc[a][cc]);
    if (l < CHH) {
        atomicAdd(&g_nq[b * CDIM + hd * CHH + l], nqp);
        atomicAdd(&g_nk[b * CDIM + hd * CHH + l], nkp);
    }
}

// ---------------------------------------------------------------------------
// Softmax + W_eff = W_proj @ A_blockdiag, emitted bf16 hi/lo [192][192]
// ---------------------------------------------------------------------------
__global__ void softmax_weff_kernel(const float* __restrict__ temp,
                                    const float* __restrict__ Wp)
{
    const int b = blockIdx.x;
    const int t = threadIdx.x;            // 384
    __shared__ float A[HEADS][CHH][CHH];
    __shared__ float qinv[CDIM], kinv[CDIM];

    if (t < CDIM) {
        qinv[t] = 1.0f / fmaxf(sqrtf(g_nq[b * CDIM + t]), 1e-12f);
    } else if (t < 2 * CDIM) {
        int c = t - CDIM;
        kinv[c] = 1.0f / fmaxf(sqrtf(g_nk[b * CDIM + c]), 1e-12f);
    }
    __syncthreads();

    if (t < CDIM) {
        const int hd = t / CHH, i = t % CHH;
        const float tp = temp[hd];
        const float qi = qinv[hd * CHH + i];
        float row[CHH];
        float m = -1e30f;
#pragma unroll
        for (int j = 0; j < CHH; ++j) {
            float v = g_gram[((b * HEADS + hd) * CHH + i) * CHH + j]
                      * tp * qi * kinv[hd * CHH + j];
            row[j] = v;
            m = fmaxf(m, v);
        }
        float ssum = 0.f;
#pragma unroll
        for (int j = 0; j < CHH; ++j) { row[j] = expf(row[j] - m); ssum += row[j]; }
        float inv = 1.0f / ssum;
#pragma unroll
        for (int j = 0; j < CHH; ++j) A[hd][i][j] = row[j] * inv;
    }
    __syncthreads();

    for (int idx = t; idx < CDIM * CDIM; idx += 384) {
        const int o = idx / CDIM, cc = idx % CDIM;
        const int hd = cc / CHH, j = cc % CHH;
        float s = 0.f;
#pragma unroll
        for (int i = 0; i < CHH; ++i)
            s += Wp[o * CDIM + hd * CHH + i] * A[hd][i][j];
        __nv_bfloat16 h = __float2bfloat16(s);
        g_weff_hi[(long long)b * CDIM * CDIM + idx] = h;
        g_weff_lo[(long long)b * CDIM * CDIM + idx] =
            __float2bfloat16(s - __bfloat162float(h));
    }
}

// ---------------------------------------------------------------------------
extern "C" void kernel_launch(void* const* d_in, const int* in_sizes, int n_in,
                              void* d_out, int out_size)
{
    (void)in_sizes; (void)n_in; (void)out_size;
    const float* x     = (const float*)d_in[0];
    const float* feat  = (const float*)d_in[1];
    const float* Wqkv  = (const float*)d_in[2];
    const float* Wdw   = (const float*)d_in[3];
    const float* Wproj = (const float*)d_in[4];
    const float* temp  = (const float*)d_in[5];
    float* out = (float*)d_out;

    float *qkv1, *qkv2;
    __nv_bfloat16 *wqh, *wql, *wfh, *wfl;
    cudaGetSymbolAddress((void**)&qkv1, g_qkv1);
    cudaGetSymbolAddress((void**)&qkv2, g_qkv2);
    cudaGetSymbolAddress((void**)&wqh, g_wq_hi);
    cudaGetSymbolAddress((void**)&wql, g_wq_lo);
    cudaGetSymbolAddress((void**)&wfh, g_weff_hi);
    cudaGetSymbolAddress((void**)&wfl, g_weff_lo);

    static int smem_set = 0;
    if (!smem_set) {
        cudaFuncSetAttribute(gemm_mma, cudaFuncAttributeMaxDynamicSharedMemorySize,
                             SMEM_GEMM);
        smem_set = 1;
    }

    // 0) split W_qkv to bf16 hi/lo
    prep_wqkv_kernel<<<(C3 * CDIM + 255) / 256, 256>>>(Wqkv);

    // 1) qkv1 = W_qkv @ x  (HMMA, pipelined)
    gemm_mma<<<dim3(3, NPIX / 128, BATCH), 256, SMEM_GEMM>>>(
        wqh, wql, 0LL, x, (long long)CDIM * NPIX, qkv1, (long long)C3 * NPIX);

    // 2) 3x3 depthwise conv (vectorized)
    {
        long long total = (long long)BATCH * C3 * (NPIX / 4);
        dwconv_kernel<<<(int)((total + 255) / 256), 256>>>(qkv1, Wdw, qkv2);
    }

    // 3) Gram + norms (fused)
    zero_misc_kernel<<<(BATCH * HEADS * CHH * CHH + 255) / 256, 256>>>();
    gram_kernel<<<dim3(16, BATCH * HEADS), 256>>>(feat);

    // 4) softmax + W_eff (bf16 hi/lo)
    softmax_weff_kernel<<<BATCH, 384>>>(temp, Wproj);

    // 5) out = W_eff @ v  (HMMA, pipelined)
    gemm_mma<<<dim3(1, NPIX / 128, BATCH), 256, SMEM_GEMM>>>(
        wfh, wfl, (long long)CDIM * CDIM,
        qkv2 + (long long)2 * CDIM * NPIX, (long long)C3 * NPIX,
        out, (long long)CDIM * NPIX);
}

// round 5
// speedup vs baseline: 2.8369x; 1.2353x over previous
#include <cuda_runtime.h>
#include <cuda_fp16.h>
#include <math.h>
#include <stdint.h>

#define BATCH 8
#define CDIM 192
#define C3 576
#define HEADS 8
#define CHH 24
#define NPIX 16384
#define IMW 128

// ---------------- scratch (device globals; allocation-free rule) ------------
__device__ float g_qkv1[BATCH * C3 * NPIX];
__device__ float g_qkv2[BATCH * C3 * NPIX];
__device__ float g_gram[BATCH * HEADS * CHH * CHH];
__device__ float g_nq[BATCH * CDIM];
__device__ float g_nk[BATCH * CDIM];
__device__ __half g_wq_hi[C3 * CDIM];
__device__ __half g_wq_lo[C3 * CDIM];
__device__ __half g_weff_hi[BATCH * CDIM * CDIM];
__device__ __half g_weff_lo[BATCH * CDIM * CDIM];

#define MMA_F16(d, a, bb) \
    asm volatile("mma.sync.aligned.m16n8k16.row.col.f32.f16.f16.f32 " \
        "{%0,%1,%2,%3}, {%4,%5,%6,%7}, {%8,%9}, {%0,%1,%2,%3};" \
        : "+f"((d)[0]), "+f"((d)[1]), "+f"((d)[2]), "+f"((d)[3]) \
        : "r"((a)[0]), "r"((a)[1]), "r"((a)[2]), "r"((a)[3]), \
          "r"((bb)[0]), "r"((bb)[1]))

__device__ __forceinline__ uint32_t pack_h2(__half a, __half b) {
    return ((uint32_t)__half_as_ushort(b) << 16) | __half_as_ushort(a);
}
__device__ __forceinline__ uint32_t smem_u32(const void* p) {
    uint32_t a;
    asm("{ .reg .u64 t; cvta.to.shared.u64 t, %1; cvt.u32.u64 %0, t; }"
        : "=r"(a) : "l"(p));
    return a;
}
__device__ __forceinline__ void cp_async16(uint32_t dst, const void* src) {
    asm volatile("cp.async.cg.shared.global [%0], [%1], 16;" :: "r"(dst), "l"(src));
}

// ---------------------------------------------------------------------------
// HMMA GEMM: Y[o,n] = sum_c W[o,c] X[c,n] per batch. fp16: W split hi/lo
// (exact to ~22 bits), X rounded to single fp16 (error ~2^-12). 2 MMA passes.
// BM=192, BN=128, BK=32, K=192. 256 threads (8 warps: 4M x 2N; 48x64/warp).
// Full A (hi/lo) loaded once via cp.async; B register-prefetched (LDG.128).
// ---------------------------------------------------------------------------
#define LDAE 200
#define LDB  40
#define SMEM_GEMM ((2 * 192 * LDAE + 128 * LDB) * 2)   // 163840 bytes

__global__ __launch_bounds__(256, 1)
void gemm_mma(const __half* __restrict__ Whi,
              const __half* __restrict__ Wlo,
              long long wstride,
              const float* __restrict__ X, long long xstride,
              float* __restrict__ Y, long long ystride)
{
    extern __shared__ __half smem[];
    __half* Ah = smem;
    __half* Al = Ah + 192 * LDAE;
    __half* Bh = Al + 192 * LDAE;

    const int b = blockIdx.z;
    const int o0 = blockIdx.x * 192;
    const int n0 = blockIdx.y * 128;
    const __half* Wh = Whi + (long long)b * wstride;
    const __half* Wl = Wlo + (long long)b * wstride;
    const float* Xp = X + (long long)b * xstride;
    float* Yp = Y + (long long)b * ystride;

    const int tid = threadIdx.x;
    const int lane = tid & 31;
    const int wid = tid >> 5;
    const int wm = wid & 3;
    const int wn = wid >> 2;

    // ---- async load of full A (hi + lo) ----
    {
        const uint32_t ah = smem_u32(Ah), al = smem_u32(Al);
#pragma unroll
        for (int c = 0; c < 18; ++c) {
            int ch = c * 256 + tid;            // 0..4607
            int row = ch / 24, col = ch % 24;  // 16B chunks (8 halves)
            uint32_t doff = (uint32_t)(row * LDAE + col * 8) * 2u;
            long long soff = (long long)(o0 + row) * CDIM + col * 8;
            cp_async16(ah + doff, Wh + soff);
            cp_async16(al + doff, Wl + soff);
        }
        asm volatile("cp.async.commit_group;");
    }

    float acc[3][8][4];
#pragma unroll
    for (int mi = 0; mi < 3; ++mi)
#pragma unroll
        for (int ni = 0; ni < 8; ++ni)
#pragma unroll
            for (int q = 0; q < 4; ++q) acc[mi][ni][q] = 0.f;

    // ---- B prefetch regs ----
    const int kr = (tid >> 5) * 2;        // even k row
    const int nc = (tid & 31) * 4;        // n within tile
    float4 pb[2][2];
#pragma unroll
    for (int j = 0; j < 2; ++j)
#pragma unroll
        for (int r = 0; r < 2; ++r)
            pb[j][r] = *reinterpret_cast<const float4*>(
                &Xp[(long long)(j * 16 + kr + r) * NPIX + n0 + nc]);

    asm volatile("cp.async.wait_group 0;");
    __syncthreads();

    for (int kt = 0; kt < 6; ++kt) {
        // ---- store B tile: fp32 -> fp16, k-pairs packed ----
#pragma unroll
        for (int j = 0; j < 2; ++j) {
            const int kk = j * 16 + kr;
            float e0[4] = {pb[j][0].x, pb[j][0].y, pb[j][0].z, pb[j][0].w};
            float e1[4] = {pb[j][1].x, pb[j][1].y, pb[j][1].z, pb[j][1].w};
#pragma unroll
            for (int i = 0; i < 4; ++i)
                *reinterpret_cast<uint32_t*>(&Bh[(nc + i) * LDB + kk]) =
                    pack_h2(__float2half(e0[i]), __float2half(e1[i]));
        }
        __syncthreads();

        // ---- prefetch next B tile ----
        if (kt < 5) {
#pragma unroll
            for (int j = 0; j < 2; ++j)
#pragma unroll
                for (int r = 0; r < 2; ++r)
                    pb[j][r] = *reinterpret_cast<const float4*>(
                        &Xp[(long long)((kt + 1) * 32 + j * 16 + kr + r) * NPIX + n0 + nc]);
        }

        // ---- compute: 2 k-steps of 16 ----
#pragma unroll
        for (int ks = 0; ks < 2; ++ks) {
            const int kga = kt * 32 + ks * 16 + (lane & 3) * 2;
            const int kb = ks * 16 + (lane & 3) * 2;
            uint32_t fah[3][4], fal[3][4];
#pragma unroll
            for (int mi = 0; mi < 3; ++mi) {
                int rb = wm * 48 + mi * 16 + (lane >> 2);
                fah[mi][0] = *reinterpret_cast<const uint32_t*>(&Ah[rb * LDAE + kga]);
                fah[mi][1] = *reinterpret_cast<const uint32_t*>(&Ah[(rb + 8) * LDAE + kga]);
                fah[mi][2] = *reinterpret_cast<const uint32_t*>(&Ah[rb * LDAE + kga + 8]);
                fah[mi][3] = *reinterpret_cast<const uint32_t*>(&Ah[(rb + 8) * LDAE + kga + 8]);
                fal[mi][0] = *reinterpret_cast<const uint32_t*>(&Al[rb * LDAE + kga]);
                fal[mi][1] = *reinterpret_cast<const uint32_t*>(&Al[(rb + 8) * LDAE + kga]);
                fal[mi][2] = *reinterpret_cast<const uint32_t*>(&Al[rb * LDAE + kga + 8]);
                fal[mi][3] = *reinterpret_cast<const uint32_t*>(&Al[(rb + 8) * LDAE + kga + 8]);
            }
            uint32_t fbh[8][2];
#pragma unroll
            for (int ni = 0; ni < 8; ++ni) {
                int cb = wn * 64 + ni * 8 + (lane >> 2);
                fbh[ni][0] = *reinterpret_cast<const uint32_t*>(&Bh[cb * LDB + kb]);
                fbh[ni][1] = *reinterpret_cast<const uint32_t*>(&Bh[cb * LDB + kb + 8]);
            }
#pragma unroll
            for (int mi = 0; mi < 3; ++mi)
#pragma unroll
                for (int ni = 0; ni < 8; ++ni) {
                    MMA_F16(acc[mi][ni], fah[mi], fbh[ni]);
                    MMA_F16(acc[mi][ni], fal[mi], fbh[ni]);
                }
        }
        __syncthreads();
    }

    // ---- epilogue ----
#pragma unroll
    for (int mi = 0; mi < 3; ++mi) {
        int r = o0 + wm * 48 + mi * 16 + (lane >> 2);
#pragma unroll
        for (int ni = 0; ni < 8; ++ni) {
            int c = n0 + wn * 64 + ni * 8 + (lane & 3) * 2;
            *reinterpret_cast<float2*>(&Yp[(long long)r * NPIX + c]) =
                make_float2(acc[mi][ni][0], acc[mi][ni][1]);
            *reinterpret_cast<float2*>(&Yp[(long long)(r + 8) * NPIX + c]) =
                make_float2(acc[mi][ni][2], acc[mi][ni][3]);
        }
    }
}

// ---------------------------------------------------------------------------
// Weight prep: fp32 -> fp16 hi/lo (half the rows per launch; 2 launches)
// ---------------------------------------------------------------------------
__global__ void prep_wqkv_kernel(const float* __restrict__ W, int base)
{
    int idx = base + blockIdx.x * blockDim.x + threadIdx.x;
    if (idx >= C3 * CDIM) return;
    float v = W[idx];
    __half h = __float2half(v);
    g_wq_hi[idx] = h;
    g_wq_lo[idx] = __float2half(v - __half2float(h));
}

// ---------------------------------------------------------------------------
// 3x3 depthwise conv, padding 1; 4 pixels per thread (float4)
// ---------------------------------------------------------------------------
__global__ void dwconv_kernel(const float* __restrict__ in,
                              const float* __restrict__ wdw,
                              float* __restrict__ out)
{
    long long idx = (long long)blockIdx.x * blockDim.x + threadIdx.x;
    if (idx >= (long long)BATCH * C3 * (NPIX / 4)) return;
    const int n4 = (int)(idx & (NPIX / 4 - 1));
    const int ch = (int)(idx >> 12);
    const int oc = ch % C3;
    const int y = n4 >> 5;
    const int x0 = (n4 & 31) * 4;
    const float* w = wdw + oc * 9;
    const float* p = in + (long long)ch * NPIX;

    float4 o = make_float4(0.f, 0.f, 0.f, 0.f);
#pragma unroll
    for (int r = 0; r < 3; ++r) {
        int yy = y + r - 1;
        if (yy < 0 || yy > IMW - 1) continue;
        const float* row = p + yy * IMW;
        float4 c = *reinterpret_cast<const float4*>(&row[x0]);
        float lft = (x0 > 0) ? row[x0 - 1] : 0.f;
        float rgt = (x0 < IMW - 4) ? row[x0 + 4] : 0.f;
        float w0 = w[r * 3], w1 = w[r * 3 + 1], w2 = w[r * 3 + 2];
        o.x += w0 * lft + w1 * c.x + w2 * c.y;
        o.y += w0 * c.x + w1 * c.y + w2 * c.z;
        o.z += w0 * c.y + w1 * c.z + w2 * c.w;
        o.w += w0 * c.z + w1 * c.w + w2 * rgt;
    }
    *reinterpret_cast<float4*>(&out[(long long)ch * NPIX + y * IMW + x0]) = o;
}

__global__ void zero_misc_kernel()
{
    int i = blockIdx.x * blockDim.x + threadIdx.x;
    if (i < BATCH * HEADS * CHH * CHH) g_gram[i] = 0.f;
    if (i < BATCH * CDIM) { g_nq[i] = 0.f; g_nk[i] = 0.f; }
}

// ---------------------------------------------------------------------------
// Gram + fused norms
// ---------------------------------------------------------------------------
__global__ void gram_kernel(const float* __restrict__ feat)
{
    __shared__ float QF[4][CHH][64];
    __shared__ float KF[4][CHH][64];

    const int bh = blockIdx.y;
    const int b = bh >> 3, hd = bh & 7;
    const int n0 = blockIdx.x * 1024;
    const int t = threadIdx.x;
    const int g = t >> 6, l = t & 63;
    const int li = l >> 3, lj = l & 7;
    const int i0 = li * 3, j0 = lj * 3;

    const float* qbase = g_qkv2 + ((long long)b * C3 + hd * CHH) * NPIX;
    const float* kbase = g_qkv2 + ((long long)b * C3 + CDIM + hd * CHH) * NPIX;
    const float* fbase = feat + ((long long)b * CDIM + hd * CHH) * NPIX;

    float acc[3][3];
#pragma unroll
    for (int a = 0; a < 3; ++a)
#pragma unroll
        for (int cc = 0; cc < 3; ++cc) acc[a][cc] = 0.f;
    float nqp = 0.f, nkp = 0.f;

    for (int s = 0; s < 1024; s += 256) {
        const int nb = n0 + s + g * 64;
        for (int e = l; e < CHH * 64; e += 64) {
            int i = e >> 6, nn = e & 63;
            long long off = (long long)i * NPIX + nb + nn;
            float fv = fbase[off];
            QF[g][i][nn] = qbase[off] * fv;
            KF[g][i][nn] = kbase[off] * fv;
        }
        __syncthreads();
#pragma unroll 4
        for (int it = 0; it < 64; ++it) {
            int nn = (it + l) & 63;
            float q0 = QF[g][i0 + 0][nn];
            float q1 = QF[g][i0 + 1][nn];
            float q2 = QF[g][i0 + 2][nn];
            float k0 = KF[g][j0 + 0][nn];
            float k1 = KF[g][j0 + 1][nn];
            float k2 = KF[g][j0 + 2][nn];
            acc[0][0] += q0 * k0; acc[0][1] += q0 * k1; acc[0][2] += q0 * k2;
            acc[1][0] += q1 * k0; acc[1][1] += q1 * k1; acc[1][2] += q1 * k2;
            acc[2][0] += q2 * k0; acc[2][1] += q2 * k1; acc[2][2] += q2 * k2;
        }
        if (l < CHH) {
#pragma unroll 4
            for (int it = 0; it < 64; ++it) {
                int nn = (it + l) & 63;
                float qv = QF[g][l][nn]; nqp += qv * qv;
                float kv = KF[g][l][nn]; nkp += kv * kv;
            }
        }
        __syncthreads();
    }

#pragma unroll
    for (int a = 0; a < 3; ++a)
#pragma unroll
        for (int cc = 0; cc < 3; ++cc)
            atomicAdd(&g_gram[(bh * CHH + i0 + a) * CHH + j0 + cc], acc[a][cc]);
    if (l < CHH) {
        atomicAdd(&g_nq[b * CDIM + hd * CHH + l], nqp);
        atomicAdd(&g_nk[b * CDIM + hd * CHH + l], nkp);
    }
}

// ---------------------------------------------------------------------------
// Softmax + W_eff = W_proj @ A_blockdiag, emitted fp16 hi/lo [192][192]
// ---------------------------------------------------------------------------
__global__ void softmax_weff_kernel(const float* __restrict__ temp,
                                    const float* __restrict__ Wp)
{
    const int b = blockIdx.x;
    const int t = threadIdx.x;            // 384
    __shared__ float A[HEADS][CHH][CHH];
    __shared__ float qinv[CDIM], kinv[CDIM];

    if (t < CDIM) {
        qinv[t] = 1.0f / fmaxf(sqrtf(g_nq[b * CDIM + t]), 1e-12f);
    } else if (t < 2 * CDIM) {
        int c = t - CDIM;
        kinv[c] = 1.0f / fmaxf(sqrtf(g_nk[b * CDIM + c]), 1e-12f);
    }
    __syncthreads();

    if (t < CDIM) {
        const int hd = t / CHH, i = t % CHH;
        const float tp = temp[hd];
        const float qi = qinv[hd * CHH + i];
        float row[CHH];
        float m = -1e30f;
#pragma unroll
        for (int j = 0; j < CHH; ++j) {
            float v = g_gram[((b * HEADS + hd) * CHH + i) * CHH + j]
                      * tp * qi * kinv[hd * CHH + j];
            row[j] = v;
            m = fmaxf(m, v);
        }
        float ssum = 0.f;
#pragma unroll
        for (int j = 0; j < CHH; ++j) { row[j] = expf(row[j] - m); ssum += row[j]; }
        float inv = 1.0f / ssum;
#pragma unroll
        for (int j = 0; j < CHH; ++j) A[hd][i][j] = row[j] * inv;
    }
    __syncthreads();

    for (int idx = t; idx < CDIM * CDIM; idx += 384) {
        const int o = idx / CDIM, cc = idx % CDIM;
        const int hd = cc / CHH, j = cc % CHH;
        float s = 0.f;
#pragma unroll
        for (int i = 0; i < CHH; ++i)
            s += Wp[o * CDIM + hd * CHH + i] * A[hd][i][j];
        __half h = __float2half(s);
        g_weff_hi[(long long)b * CDIM * CDIM + idx] = h;
        g_weff_lo[(long long)b * CDIM * CDIM + idx] =
            __float2half(s - __half2float(h));
    }
}

// ---------------------------------------------------------------------------
extern "C" void kernel_launch(void* const* d_in, const int* in_sizes, int n_in,
                              void* d_out, int out_size)
{
    (void)in_sizes; (void)n_in; (void)out_size;
    const float* x     = (const float*)d_in[0];
    const float* feat  = (const float*)d_in[1];
    const float* Wqkv  = (const float*)d_in[2];
    const float* Wdw   = (const float*)d_in[3];
    const float* Wproj = (const float*)d_in[4];
    const float* temp  = (const float*)d_in[5];
    float* out = (float*)d_out;

    float *qkv1, *qkv2;
    __half *wqh, *wql, *wfh, *wfl;
    cudaGetSymbolAddress((void**)&qkv1, g_qkv1);
    cudaGetSymbolAddress((void**)&qkv2, g_qkv2);
    cudaGetSymbolAddress((void**)&wqh, g_wq_hi);
    cudaGetSymbolAddress((void**)&wql, g_wq_lo);
    cudaGetSymbolAddress((void**)&wfh, g_weff_hi);
    cudaGetSymbolAddress((void**)&wfl, g_weff_lo);

    static int smem_set = 0;
    if (!smem_set) {
        cudaFuncSetAttribute(gemm_mma, cudaFuncAttributeMaxDynamicSharedMemorySize,
                             SMEM_GEMM);
        smem_set = 1;
    }

    const int HALF_W = C3 * CDIM / 2;   // 55296

    // Launch order puts gemm1 at slot 4 (ncu profiles the 4th launch).
    // 1) zero gram/norm accumulators
    zero_misc_kernel<<<(BATCH * HEADS * CHH * CHH + 255) / 256, 256>>>();
    // 2,3) split W_qkv to fp16 hi/lo (two halves)
    prep_wqkv_kernel<<<(HALF_W + 255) / 256, 256>>>(Wqkv, 0);
    prep_wqkv_kernel<<<(HALF_W + 255) / 256, 256>>>(Wqkv, HALF_W);

    // 4) qkv1 = W_qkv @ x  (HMMA fp16 2-pass)
    gemm_mma<<<dim3(3, NPIX / 128, BATCH), 256, SMEM_GEMM>>>(
        wqh, wql, 0LL, x, (long long)CDIM * NPIX, qkv1, (long long)C3 * NPIX);

    // 5) 3x3 depthwise conv (vectorized)
    {
        long long total = (long long)BATCH * C3 * (NPIX / 4);
        dwconv_kernel<<<(int)((total + 255) / 256), 256>>>(qkv1, Wdw, qkv2);
    }

    // 6) Gram + norms (fused)
    gram_kernel<<<dim3(16, BATCH * HEADS), 256>>>(feat);

    // 7) softmax + W_eff (fp16 hi/lo)
    softmax_weff_kernel<<<BATCH, 384>>>(temp, Wproj);

    // 8) out = W_eff @ v  (HMMA fp16 2-pass)
    gemm_mma<<<dim3(1, NPIX / 128, BATCH), 256, SMEM_GEMM>>>(
        wfh, wfl, (long long)CDIM * CDIM,
        qkv2 + (long long)2 * CDIM * NPIX, (long long)C3 * NPIX,
        out, (long long)CDIM * NPIX);
}

// round 6
// speedup vs baseline: 3.0844x; 1.0872x over previous
#include <cuda_runtime.h>
#include <cuda_fp16.h>
#include <math.h>
#include <stdint.h>

#define BATCH 8
#define CDIM 192
#define C3 576
#define HEADS 8
#define CHH 24
#define NPIX 16384
#define IMW 128

// ---------------- scratch (device globals; allocation-free rule) ------------
__device__ float g_qkv1[BATCH * C3 * NPIX];
__device__ float g_qkv2[BATCH * C3 * NPIX];
__device__ float g_gram[BATCH * HEADS * CHH * CHH];
__device__ float g_nq[BATCH * CDIM];
__device__ float g_nk[BATCH * CDIM];
__device__ __half g_wq_hi[C3 * CDIM];
__device__ __half g_wq_lo[C3 * CDIM];
__device__ __half g_weff_hi[BATCH * CDIM * CDIM];
__device__ __half g_weff_lo[BATCH * CDIM * CDIM];

#define MMA_F16(d, a, bb) \
    asm volatile("mma.sync.aligned.m16n8k16.row.col.f32.f16.f16.f32 " \
        "{%0,%1,%2,%3}, {%4,%5,%6,%7}, {%8,%9}, {%0,%1,%2,%3};" \
        : "+f"((d)[0]), "+f"((d)[1]), "+f"((d)[2]), "+f"((d)[3]) \
        : "r"((a)[0]), "r"((a)[1]), "r"((a)[2]), "r"((a)[3]), \
          "r"((bb)[0]), "r"((bb)[1]))

#define LDSM_X4(r0, r1, r2, r3, addr) \
    asm volatile("ldmatrix.sync.aligned.m8n8.x4.shared.b16 {%0,%1,%2,%3}, [%4];" \
        : "=r"(r0), "=r"(r1), "=r"(r2), "=r"(r3) : "r"(addr))

__device__ __forceinline__ uint32_t pack_h2(__half a, __half b) {
    return ((uint32_t)__half_as_ushort(b) << 16) | __half_as_ushort(a);
}
__device__ __forceinline__ uint32_t smem_u32(const void* p) {
    uint32_t a;
    asm("{ .reg .u64 t; cvta.to.shared.u64 t, %1; cvt.u32.u64 %0, t; }"
        : "=r"(a) : "l"(p));
    return a;
}
__device__ __forceinline__ void cp_async16(uint32_t dst, const void* src) {
    asm volatile("cp.async.cg.shared.global [%0], [%1], 16;" :: "r"(dst), "l"(src));
}

// ---------------------------------------------------------------------------
// HMMA GEMM: Y[o,n] = sum_c W[o,c] X[c,n] per batch. fp16: W split hi/lo
// (2 MMA passes), X rounded to single fp16. BM=192, BN=128, BK=32, K=192.
// 256 threads (8 warps: 4M x 2N; 48x64/warp). Full A resident in SMEM
// (cp.async once); B double-buffered, converted fp32->fp16 in-flight;
// fragments via ldmatrix.x4.
// ---------------------------------------------------------------------------
#define LDAE 200                       // A row stride (halves)
#define LDB  40                        // B row stride (halves)
#define ALO_OFF (192 * LDAE * 2)       // bytes: Al - Ah
#define B0_OFF  (2 * 192 * LDAE * 2)   // bytes: B buffer 0
#define BBUF_BYTES (128 * LDB * 2)     // 10240
#define SMEM_GEMM (B0_OFF + 2 * BBUF_BYTES)   // 174080 bytes

__global__ __launch_bounds__(256, 1)
void gemm_mma(const __half* __restrict__ Whi,
              const __half* __restrict__ Wlo,
              long long wstride,
              const float* __restrict__ X, long long xstride,
              float* __restrict__ Y, long long ystride)
{
    extern __shared__ __half smem[];
    __half* Ah = smem;
    __half* Bb = reinterpret_cast<__half*>(reinterpret_cast<char*>(smem) + B0_OFF);

    const int b = blockIdx.z;
    const int o0 = blockIdx.x * 192;
    const int n0 = blockIdx.y * 128;
    const __half* Wh = Whi + (long long)b * wstride;
    const __half* Wl = Wlo + (long long)b * wstride;
    const float* Xp = X + (long long)b * xstride;
    float* Yp = Y + (long long)b * ystride;

    const int tid = threadIdx.x;
    const int lane = tid & 31;
    const int wid = tid >> 5;
    const int wm = wid & 3;
    const int wn = wid >> 2;

    // ---- async load of full A (hi + lo) ----
    {
        const uint32_t ah = smem_u32(Ah);
#pragma unroll
        for (int c = 0; c < 18; ++c) {
            int ch = c * 256 + tid;            // 0..4607
            int row = ch / 24, col = ch % 24;  // 16B chunks (8 halves)
            uint32_t doff = (uint32_t)(row * LDAE + col * 8) * 2u;
            long long soff = (long long)(o0 + row) * CDIM + col * 8;
            cp_async16(ah + doff, Wh + soff);
            cp_async16(ah + ALO_OFF + doff, Wl + soff);
        }
        asm volatile("cp.async.commit_group;");
    }

    float acc[3][8][4];
#pragma unroll
    for (int mi = 0; mi < 3; ++mi)
#pragma unroll
        for (int ni = 0; ni < 8; ++ni)
#pragma unroll
            for (int q = 0; q < 4; ++q) acc[mi][ni][q] = 0.f;

    // ---- ldmatrix per-lane addresses ----
    const int lg = lane >> 3, lr = lane & 7;
    const uint32_t a_base = smem_u32(Ah);
    const uint32_t b_base = smem_u32(Bb);
    uint32_t a_row[3];
#pragma unroll
    for (int mi = 0; mi < 3; ++mi) {
        int row = wm * 48 + mi * 16 + (lg & 1) * 8 + lr;
        a_row[mi] = a_base + (uint32_t)(row * LDAE + (lg >> 1) * 8) * 2u;
    }
    uint32_t b_row[4];
#pragma unroll
    for (int nj = 0; nj < 4; ++nj) {
        int n = wn * 64 + (nj * 2 + (lg >> 1)) * 8 + lr;
        b_row[nj] = (uint32_t)(n * LDB + (lg & 1) * 8) * 2u;
    }

    // ---- B conversion lane mapping ----
    const int kr = (tid >> 5) * 2;        // even k row within tile
    const int nc = (tid & 31) * 4;        // n within tile
    float4 pb[2][2];
#pragma unroll
    for (int j = 0; j < 2; ++j)
#pragma unroll
        for (int r = 0; r < 2; ++r)
            pb[j][r] = *reinterpret_cast<const float4*>(
                &Xp[(long long)(j * 16 + kr + r) * NPIX + n0 + nc]);

    // prologue: convert tile 0 into buffer 0
    asm volatile("cp.async.wait_group 0;");
#pragma unroll
    for (int j = 0; j < 2; ++j) {
        const int kk = j * 16 + kr;
        float e0[4] = {pb[j][0].x, pb[j][0].y, pb[j][0].z, pb[j][0].w};
        float e1[4] = {pb[j][1].x, pb[j][1].y, pb[j][1].z, pb[j][1].w};
#pragma unroll
        for (int i = 0; i < 4; ++i)
            *reinterpret_cast<uint32_t*>(&Bb[(nc + i) * LDB + kk]) =
                pack_h2(__float2half(e0[i]), __float2half(e1[i]));
    }
    __syncthreads();

    for (int kt = 0; kt < 6; ++kt) {
        const uint32_t cur_off = (uint32_t)(kt & 1) * BBUF_BYTES;
        const uint32_t nxt_off = BBUF_BYTES - cur_off;

        // ---- prefetch next tile from gmem ----
        if (kt < 5) {
#pragma unroll
            for (int j = 0; j < 2; ++j)
#pragma unroll
                for (int r = 0; r < 2; ++r)
                    pb[j][r] = *reinterpret_cast<const float4*>(
                        &Xp[(long long)((kt + 1) * 32 + j * 16 + kr + r) * NPIX + n0 + nc]);
        }

        // ---- compute 2 ksteps from current buffer ----
#pragma unroll
        for (int ks = 0; ks < 2; ++ks) {
            const uint32_t akoff = (uint32_t)(kt * 32 + ks * 16) * 2u;
            const uint32_t bkoff = (uint32_t)(ks * 16) * 2u;
            uint32_t fah[3][4], fal[3][4], fb[8][2];
#pragma unroll
            for (int mi = 0; mi < 3; ++mi) {
                LDSM_X4(fah[mi][0], fah[mi][1], fah[mi][2], fah[mi][3],
                        a_row[mi] + akoff);
                LDSM_X4(fal[mi][0], fal[mi][1], fal[mi][2], fal[mi][3],
                        a_row[mi] + akoff + ALO_OFF);
            }
#pragma unroll
            for (int nj = 0; nj < 4; ++nj) {
                LDSM_X4(fb[2 * nj][0], fb[2 * nj][1], fb[2 * nj + 1][0], fb[2 * nj + 1][1],
                        b_base + cur_off + b_row[nj] + bkoff);
            }
#pragma unroll
            for (int mi = 0; mi < 3; ++mi)
#pragma unroll
                for (int ni = 0; ni < 8; ++ni) {
                    MMA_F16(acc[mi][ni], fah[mi], fb[ni]);
                    MMA_F16(acc[mi][ni], fal[mi], fb[ni]);
                }
        }

        // ---- convert prefetched tile into the other buffer ----
        if (kt < 5) {
            __half* Bn = reinterpret_cast<__half*>(
                reinterpret_cast<char*>(Bb) + nxt_off);
#pragma unroll
            for (int j = 0; j < 2; ++j) {
                const int kk = j * 16 + kr;
                float e0[4] = {pb[j][0].x, pb[j][0].y, pb[j][0].z, pb[j][0].w};
                float e1[4] = {pb[j][1].x, pb[j][1].y, pb[j][1].z, pb[j][1].w};
#pragma unroll
                for (int i = 0; i < 4; ++i)
                    *reinterpret_cast<uint32_t*>(&Bn[(nc + i) * LDB + kk]) =
                        pack_h2(__float2half(e0[i]), __float2half(e1[i]));
            }
        }
        __syncthreads();
    }

    // ---- epilogue ----
#pragma unroll
    for (int mi = 0; mi < 3; ++mi) {
        int r = o0 + wm * 48 + mi * 16 + (lane >> 2);
#pragma unroll
        for (int ni = 0; ni < 8; ++ni) {
            int c = n0 + wn * 64 + ni * 8 + (lane & 3) * 2;
            *reinterpret_cast<float2*>(&Yp[(long long)r * NPIX + c]) =
                make_float2(acc[mi][ni][0], acc[mi][ni][1]);
            *reinterpret_cast<float2*>(&Yp[(long long)(r + 8) * NPIX + c]) =
                make_float2(acc[mi][ni][2], acc[mi][ni][3]);
        }
    }
}

// ---------------------------------------------------------------------------
// Weight prep: fp32 -> fp16 hi/lo (two launches to fix ncu slot)
// ---------------------------------------------------------------------------
__global__ void prep_wqkv_kernel(const float* __restrict__ W, int base)
{
    int idx = base + blockIdx.x * blockDim.x + threadIdx.x;
    if (idx >= C3 * CDIM) return;
    float v = W[idx];
    __half h = __float2half(v);
    g_wq_hi[idx] = h;
    g_wq_lo[idx] = __float2half(v - __half2float(h));
}

// ---------------------------------------------------------------------------
// 3x3 depthwise conv, padding 1; 4 pixels per thread (float4)
// ---------------------------------------------------------------------------
__global__ void dwconv_kernel(const float* __restrict__ in,
                              const float* __restrict__ wdw,
                              float* __restrict__ out)
{
    long long idx = (long long)blockIdx.x * blockDim.x + threadIdx.x;
    if (idx >= (long long)BATCH * C3 * (NPIX / 4)) return;
    const int n4 = (int)(idx & (NPIX / 4 - 1));
    const int ch = (int)(idx >> 12);
    const int oc = ch % C3;
    const int y = n4 >> 5;
    const int x0 = (n4 & 31) * 4;
    const float* w = wdw + oc * 9;
    const float* p = in + (long long)ch * NPIX;

    float4 o = make_float4(0.f, 0.f, 0.f, 0.f);
#pragma unroll
    for (int r = 0; r < 3; ++r) {
        int yy = y + r - 1;
        if (yy < 0 || yy > IMW - 1) continue;
        const float* row = p + yy * IMW;
        float4 c = *reinterpret_cast<const float4*>(&row[x0]);
        float lft = (x0 > 0) ? row[x0 - 1] : 0.f;
        float rgt = (x0 < IMW - 4) ? row[x0 + 4] : 0.f;
        float w0 = w[r * 3], w1 = w[r * 3 + 1], w2 = w[r * 3 + 2];
        o.x += w0 * lft + w1 * c.x + w2 * c.y;
        o.y += w0 * c.x + w1 * c.y + w2 * c.z;
        o.z += w0 * c.y + w1 * c.z + w2 * c.w;
        o.w += w0 * c.z + w1 * c.w + w2 * rgt;
    }
    *reinterpret_cast<float4*>(&out[(long long)ch * NPIX + y * IMW + x0]) = o;
}

__global__ void zero_misc_kernel()
{
    int i = blockIdx.x * blockDim.x + threadIdx.x;
    if (i < BATCH * HEADS * CHH * CHH) g_gram[i] = 0.f;
    if (i < BATCH * CDIM) { g_nq[i] = 0.f; g_nk[i] = 0.f; }
}

// ---------------------------------------------------------------------------
// Gram + fused norms
// ---------------------------------------------------------------------------
__global__ void gram_kernel(const float* __restrict__ feat)
{
    __shared__ float QF[4][CHH][64];
    __shared__ float KF[4][CHH][64];

    const int bh = blockIdx.y;
    const int b = bh >> 3, hd = bh & 7;
    const int n0 = blockIdx.x * 1024;
    const int t = threadIdx.x;
    const int g = t >> 6, l = t & 63;
    const int li = l >> 3, lj = l & 7;
    const int i0 = li * 3, j0 = lj * 3;

    const float* qbase = g_qkv2 + ((long long)b * C3 + hd * CHH) * NPIX;
    const float* kbase = g_qkv2 + ((long long)b * C3 + CDIM + hd * CHH) * NPIX;
    const float* fbase = feat + ((long long)b * CDIM + hd * CHH) * NPIX;

    float acc[3][3];
#pragma unroll
    for (int a = 0; a < 3; ++a)
#pragma unroll
        for (int cc = 0; cc < 3; ++cc) acc[a][cc] = 0.f;
    float nqp = 0.f, nkp = 0.f;

    for (int s = 0; s < 1024; s += 256) {
        const int nb = n0 + s + g * 64;
        for (int e = l; e < CHH * 64; e += 64) {
            int i = e >> 6, nn = e & 63;
            long long off = (long long)i * NPIX + nb + nn;
            float fv = fbase[off];
            QF[g][i][nn] = qbase[off] * fv;
            KF[g][i][nn] = kbase[off] * fv;
        }
        __syncthreads();
#pragma unroll 4
        for (int it = 0; it < 64; ++it) {
            int nn = (it + l) & 63;
            float q0 = QF[g][i0 + 0][nn];
            float q1 = QF[g][i0 + 1][nn];
            float q2 = QF[g][i0 + 2][nn];
            float k0 = KF[g][j0 + 0][nn];
            float k1 = KF[g][j0 + 1][nn];
            float k2 = KF[g][j0 + 2][nn];
            acc[0][0] += q0 * k0; acc[0][1] += q0 * k1; acc[0][2] += q0 * k2;
            acc[1][0] += q1 * k0; acc[1][1] += q1 * k1; acc[1][2] += q1 * k2;
            acc[2][0] += q2 * k0; acc[2][1] += q2 * k1; acc[2][2] += q2 * k2;
        }
        if (l < CHH) {
#pragma unroll 4
            for (int it = 0; it < 64; ++it) {
                int nn = (it + l) & 63;
                float qv = QF[g][l][nn]; nqp += qv * qv;
                float kv = KF[g][l][nn]; nkp += kv * kv;
            }
        }
        __syncthreads();
    }

#pragma unroll
    for (int a = 0; a < 3; ++a)
#pragma unroll
        for (int cc = 0; cc < 3; ++cc)
            atomicAdd(&g_gram[(bh * CHH + i0 + a) * CHH + j0 + cc], acc[a][cc]);
    if (l < CHH) {
        atomicAdd(&g_nq[b * CDIM + hd * CHH + l], nqp);
        atomicAdd(&g_nk[b * CDIM + hd * CHH + l], nkp);
    }
}

// ---------------------------------------------------------------------------
// Softmax + W_eff = W_proj @ A_blockdiag, emitted fp16 hi/lo [192][192]
// ---------------------------------------------------------------------------
__global__ void softmax_weff_kernel(const float* __restrict__ temp,
                                    const float* __restrict__ Wp)
{
    const int b = blockIdx.x;
    const int t = threadIdx.x;            // 384
    __shared__ float A[HEADS][CHH][CHH];
    __shared__ float qinv[CDIM], kinv[CDIM];

    if (t < CDIM) {
        qinv[t] = 1.0f / fmaxf(sqrtf(g_nq[b * CDIM + t]), 1e-12f);
    } else if (t < 2 * CDIM) {
        int c = t - CDIM;
        kinv[c] = 1.0f / fmaxf(sqrtf(g_nk[b * CDIM + c]), 1e-12f);
    }
    __syncthreads();

    if (t < CDIM) {
        const int hd = t / CHH, i = t % CHH;
        const float tp = temp[hd];
        const float qi = qinv[hd * CHH + i];
        float row[CHH];
        float m = -1e30f;
#pragma unroll
        for (int j = 0; j < CHH; ++j) {
            float v = g_gram[((b * HEADS + hd) * CHH + i) * CHH + j]
                      * tp * qi * kinv[hd * CHH + j];
            row[j] = v;
            m = fmaxf(m, v);
        }
        float ssum = 0.f;
#pragma unroll
        for (int j = 0; j < CHH; ++j) { row[j] = expf(row[j] - m); ssum += row[j]; }
        float inv = 1.0f / ssum;
#pragma unroll
        for (int j = 0; j < CHH; ++j) A[hd][i][j] = row[j] * inv;
    }
    __syncthreads();

    for (int idx = t; idx < CDIM * CDIM; idx += 384) {
        const int o = idx / CDIM, cc = idx % CDIM;
        const int hd = cc / CHH, j = cc % CHH;
        float s = 0.f;
#pragma unroll
        for (int i = 0; i < CHH; ++i)
            s += Wp[o * CDIM + hd * CHH + i] * A[hd][i][j];
        __half h = __float2half(s);
        g_weff_hi[(long long)b * CDIM * CDIM + idx] = h;
        g_weff_lo[(long long)b * CDIM * CDIM + idx] =
            __float2half(s - __half2float(h));
    }
}

// ---------------------------------------------------------------------------
extern "C" void kernel_launch(void* const* d_in, const int* in_sizes, int n_in,
                              void* d_out, int out_size)
{
    (void)in_sizes; (void)n_in; (void)out_size;
    const float* x     = (const float*)d_in[0];
    const float* feat  = (const float*)d_in[1];
    const float* Wqkv  = (const float*)d_in[2];
    const float* Wdw   = (const float*)d_in[3];
    const float* Wproj = (const float*)d_in[4];
    const float* temp  = (const float*)d_in[5];
    float* out = (float*)d_out;

    float *qkv1, *qkv2;
    __half *wqh, *wql, *wfh, *wfl;
    cudaGetSymbolAddress((void**)&qkv1, g_qkv1);
    cudaGetSymbolAddress((void**)&qkv2, g_qkv2);
    cudaGetSymbolAddress((void**)&wqh, g_wq_hi);
    cudaGetSymbolAddress((void**)&wql, g_wq_lo);
    cudaGetSymbolAddress((void**)&wfh, g_weff_hi);
    cudaGetSymbolAddress((void**)&wfl, g_weff_lo);

    static int smem_set = 0;
    if (!smem_set) {
        cudaFuncSetAttribute(gemm_mma, cudaFuncAttributeMaxDynamicSharedMemorySize,
                             SMEM_GEMM);
        smem_set = 1;
    }

    const int HALF_W = C3 * CDIM / 2;

    // Launch order keeps gemm1 at ncu slot 4.
    zero_misc_kernel<<<(BATCH * HEADS * CHH * CHH + 255) / 256, 256>>>();
    prep_wqkv_kernel<<<(HALF_W + 255) / 256, 256>>>(Wqkv, 0);
    prep_wqkv_kernel<<<(HALF_W + 255) / 256, 256>>>(Wqkv, HALF_W);

    // 4) qkv1 = W_qkv @ x
    gemm_mma<<<dim3(3, NPIX / 128, BATCH), 256, SMEM_GEMM>>>(
        wqh, wql, 0LL, x, (long long)CDIM * NPIX, qkv1, (long long)C3 * NPIX);

    // 5) depthwise conv
    {
        long long total = (long long)BATCH * C3 * (NPIX / 4);
        dwconv_kernel<<<(int)((total + 255) / 256), 256>>>(qkv1, Wdw, qkv2);
    }

    // 6) Gram + norms
    gram_kernel<<<dim3(16, BATCH * HEADS), 256>>>(feat);

    // 7) softmax + W_eff
    softmax_weff_kernel<<<BATCH, 384>>>(temp, Wproj);

    // 8) out = W_eff @ v
    gemm_mma<<<dim3(1, NPIX / 128, BATCH), 256, SMEM_GEMM>>>(
        wfh, wfl, (long long)CDIM * CDIM,
        qkv2 + (long long)2 * CDIM * NPIX, (long long)C3 * NPIX,
        out, (long long)CDIM * NPIX);
}